// round 1
// baseline (speedup 1.0000x reference)
#include <cuda_runtime.h>

#define MARGIN 0.1f
constexpr int Bn = 8192;
constexpr int Ln = 1024;
constexpr int THREADS = 256;   // 256 threads * 4 floats = 1024 = L

// Per-row scratch (allocation-free: device globals)
__device__ float g_row_bce[Bn];
__device__ float g_row_hinge[Bn];
__device__ float g_row_valid[Bn];

__global__ void __launch_bounds__(THREADS)
row_kernel(const float4* __restrict__ scores4,
           const int*    __restrict__ lens,
           const float4* __restrict__ labels4)
{
    const int row = blockIdx.x;
    const int tid = threadIdx.x;
    const int len = lens[row];

    // One float4 of scores + labels per thread; kept in registers for both passes.
    const float4 s4 = scores4[row * THREADS + tid];
    const float4 l4 = labels4[row * THREADS + tid];
    const float sv[4] = {s4.x, s4.y, s4.z, s4.w};
    const float lv[4] = {l4.x, l4.y, l4.z, l4.w};
    const int base = tid * 4;

    float bce = 0.f, pcnt = 0.f, psum = 0.f;
#pragma unroll
    for (int k = 0; k < 4; ++k) {
        if (base + k < len) {
            const float s = sv[k];
            const float l = lv[k];
            const float lp  = fmaxf(__logf(s),        -100.f);
            const float l1m = fmaxf(__logf(1.0f - s), -100.f);
            bce -= l * lp + (1.0f - l) * l1m;
            const bool pos = (l == 1.0f);
            pcnt += pos ? 1.0f : 0.0f;
            psum += pos ? s    : 0.0f;
        }
    }

    // ---- block reduction #1 : bce, pos count, pos score sum ----
    const unsigned FULL = 0xffffffffu;
#pragma unroll
    for (int o = 16; o; o >>= 1) {
        bce  += __shfl_down_sync(FULL, bce,  o);
        pcnt += __shfl_down_sync(FULL, pcnt, o);
        psum += __shfl_down_sync(FULL, psum, o);
    }
    __shared__ float sh0[8], sh1[8], sh2[8];
    __shared__ float sh_chosen, sh_bce, sh_pcnt;
    const int w = tid >> 5, lane = tid & 31;
    if (lane == 0) { sh0[w] = bce; sh1[w] = pcnt; sh2[w] = psum; }
    __syncthreads();
    if (tid == 0) {
        float b = 0.f, p = 0.f, q = 0.f;
#pragma unroll
        for (int i = 0; i < 8; ++i) { b += sh0[i]; p += sh1[i]; q += sh2[i]; }
        sh_bce    = b;
        sh_pcnt   = p;
        sh_chosen = (p > 0.f) ? q : -MARGIN;
    }
    __syncthreads();
    const float chosen = sh_chosen;

    // ---- pass 2 from registers: hinge over valid negatives ----
    float hinge = 0.f;
#pragma unroll
    for (int k = 0; k < 4; ++k) {
        if (base + k < len && lv[k] == 0.0f)
            hinge += fmaxf(MARGIN + sv[k] - chosen, 0.0f);
    }
#pragma unroll
    for (int o = 16; o; o >>= 1)
        hinge += __shfl_down_sync(FULL, hinge, o);
    if (lane == 0) sh0[w] = hinge;
    __syncthreads();

    if (tid == 0) {
        float hsum = 0.f;
#pragma unroll
        for (int i = 0; i < 8; ++i) hsum += sh0[i];
        const float flen = (float)len;
        // bce_per = (bce_el*mask).mean(1) / mask.sum(1) = bce_sum / (L * len)
        g_row_bce[row] = sh_bce / ((float)Ln * flen);
        const float neg = flen - sh_pcnt;
        const bool  val = (len > 0) && (neg > 0.f);
        g_row_hinge[row] = val ? hsum / fmaxf(neg, 1.0f) : 0.0f;
        g_row_valid[row] = val ? 1.0f : 0.0f;
    }
}

__global__ void __launch_bounds__(1024)
final_kernel(const float* __restrict__ sim, float* __restrict__ out)
{
    const int tid = threadIdx.x;
    double b = 0.0, h = 0.0, v = 0.0, s = 0.0;
    for (int r = tid; r < Bn; r += 1024) {
        b += (double)g_row_bce[r];
        h += (double)g_row_hinge[r];
        v += (double)g_row_valid[r];
        s += (double)sim[r];
    }
    const unsigned FULL = 0xffffffffu;
#pragma unroll
    for (int o = 16; o; o >>= 1) {
        b += __shfl_down_sync(FULL, b, o);
        h += __shfl_down_sync(FULL, h, o);
        v += __shfl_down_sync(FULL, v, o);
        s += __shfl_down_sync(FULL, s, o);
    }
    __shared__ double sb[32], shh[32], svv[32], sss[32];
    const int w = tid >> 5, lane = tid & 31;
    if (lane == 0) { sb[w] = b; shh[w] = h; svv[w] = v; sss[w] = s; }
    __syncthreads();
    if (tid == 0) {
        double B2 = 0, H = 0, V = 0, S = 0;
#pragma unroll
        for (int i = 0; i < 32; ++i) { B2 += sb[i]; H += shh[i]; V += svv[i]; S += sss[i]; }
        const double bce_loss   = B2 / (double)Bn;
        const double hinge_loss = (V > 0.0) ? H / ((V > 1.0) ? V : 1.0) : 0.0;
        const double sim_loss   = -S / (double)Bn;
        const double combined   = hinge_loss + bce_loss + sim_loss;
        out[0] = (float)combined;
        out[1] = (float)hinge_loss;
        out[2] = (float)bce_loss;
        out[3] = (float)sim_loss;
    }
}

extern "C" void kernel_launch(void* const* d_in, const int* in_sizes, int n_in,
                              void* d_out, int out_size)
{
    const float4* scores4 = (const float4*)d_in[0];
    const int*    lens    = (const int*)d_in[1];
    const float4* labels4 = (const float4*)d_in[2];
    const float*  sim     = (const float*)d_in[3];
    float* out = (float*)d_out;

    row_kernel<<<Bn, THREADS>>>(scores4, lens, labels4);
    final_kernel<<<1, 1024>>>(sim, out);
}

// round 2
// speedup vs baseline: 2.2336x; 2.2336x over previous
#include <cuda_runtime.h>

#define MARGIN 0.1f
constexpr int Bn = 8192;
constexpr int Ln = 1024;
constexpr int THREADS = 256;   // 256 threads * 4 floats = 1024 = L

// Per-row scratch (allocation-free: device globals)
__device__ float g_row_bce[Bn];
__device__ float g_row_hinge[Bn];
__device__ float g_row_valid[Bn];

__global__ void __launch_bounds__(THREADS)
row_kernel(const float4* __restrict__ scores4,
           const int*    __restrict__ lens,
           const float4* __restrict__ labels4)
{
    const int row = blockIdx.x;
    const int tid = threadIdx.x;
    const int len = lens[row];

    // One float4 of scores + labels per thread; kept in registers for both passes.
    const float4 s4 = scores4[row * THREADS + tid];
    const float4 l4 = labels4[row * THREADS + tid];
    const float sv[4] = {s4.x, s4.y, s4.z, s4.w};
    const float lv[4] = {l4.x, l4.y, l4.z, l4.w};
    const int base = tid * 4;

    float bce = 0.f, pcnt = 0.f, psum = 0.f;
#pragma unroll
    for (int k = 0; k < 4; ++k) {
        const bool in = (base + k < len);
        const float s = sv[k];
        const float l = lv[k];
        const float lp  = fmaxf(__logf(s),        -100.f);
        const float l1m = fmaxf(__logf(1.0f - s), -100.f);
        const float el  = -(l * lp + (1.0f - l) * l1m);
        bce += in ? el : 0.0f;
        const bool pos = in && (l == 1.0f);
        pcnt += pos ? 1.0f : 0.0f;
        psum += pos ? s    : 0.0f;
    }

    // ---- block reduction #1 : bce, pos count, pos score sum ----
    const unsigned FULL = 0xffffffffu;
#pragma unroll
    for (int o = 16; o; o >>= 1) {
        bce  += __shfl_down_sync(FULL, bce,  o);
        pcnt += __shfl_down_sync(FULL, pcnt, o);
        psum += __shfl_down_sync(FULL, psum, o);
    }
    __shared__ float sh0[8], sh1[8], sh2[8];
    __shared__ float sh_chosen, sh_bce, sh_pcnt;
    const int w = tid >> 5, lane = tid & 31;
    if (lane == 0) { sh0[w] = bce; sh1[w] = pcnt; sh2[w] = psum; }
    __syncthreads();
    if (tid == 0) {
        float b = 0.f, p = 0.f, q = 0.f;
#pragma unroll
        for (int i = 0; i < 8; ++i) { b += sh0[i]; p += sh1[i]; q += sh2[i]; }
        sh_bce    = b;
        sh_pcnt   = p;
        sh_chosen = (p > 0.f) ? q : -MARGIN;
    }
    __syncthreads();
    const float chosen = sh_chosen;

    // ---- pass 2 from registers: hinge over valid negatives ----
    float hinge = 0.f;
#pragma unroll
    for (int k = 0; k < 4; ++k) {
        const bool neg = (base + k < len) && (lv[k] == 0.0f);
        const float h  = fmaxf(MARGIN + sv[k] - chosen, 0.0f);
        hinge += neg ? h : 0.0f;
    }
#pragma unroll
    for (int o = 16; o; o >>= 1)
        hinge += __shfl_down_sync(FULL, hinge, o);
    __syncthreads();               // protect sh0 reuse
    if (lane == 0) sh0[w] = hinge;
    __syncthreads();

    if (tid == 0) {
        float hsum = 0.f;
#pragma unroll
        for (int i = 0; i < 8; ++i) hsum += sh0[i];
        const float flen = (float)len;
        // bce_per = (bce_el*mask).mean(1) / mask.sum(1) = bce_sum / (L * len)
        g_row_bce[row] = sh_bce / ((float)Ln * flen);
        const float negc = flen - sh_pcnt;
        const bool  val  = (len > 0) && (negc > 0.f);
        g_row_hinge[row] = val ? hsum / fmaxf(negc, 1.0f) : 0.0f;
        g_row_valid[row] = val ? 1.0f : 0.0f;
    }
}

// Float-only final reduction: 8192 values per quantity, tree-reduced.
// Per-thread partial (8 values) -> warp shfl -> 32 partials -> thread 0.
// All in FP32: B300 FP64 pipe is extremely slow (R1 lesson: 33.6us -> this).
__global__ void __launch_bounds__(1024)
final_kernel(const float* __restrict__ sim, float* __restrict__ out)
{
    const int tid = threadIdx.x;
    float b = 0.f, h = 0.f, v = 0.f, s = 0.f;
#pragma unroll
    for (int i = 0; i < Bn / 1024; ++i) {
        const int r = tid + i * 1024;
        b += g_row_bce[r];
        h += g_row_hinge[r];
        v += g_row_valid[r];
        s += sim[r];
    }
    const unsigned FULL = 0xffffffffu;
#pragma unroll
    for (int o = 16; o; o >>= 1) {
        b += __shfl_down_sync(FULL, b, o);
        h += __shfl_down_sync(FULL, h, o);
        v += __shfl_down_sync(FULL, v, o);
        s += __shfl_down_sync(FULL, s, o);
    }
    __shared__ float sb[32], shh[32], svv[32], sss[32];
    const int w = tid >> 5, lane = tid & 31;
    if (lane == 0) { sb[w] = b; shh[w] = h; svv[w] = v; sss[w] = s; }
    __syncthreads();
    if (tid == 0) {
        float B2 = 0.f, H = 0.f, V = 0.f, S = 0.f;
#pragma unroll
        for (int i = 0; i < 32; ++i) { B2 += sb[i]; H += shh[i]; V += svv[i]; S += sss[i]; }
        const float bce_loss   = B2 / (float)Bn;
        const float hinge_loss = (V > 0.f) ? H / fmaxf(V, 1.0f) : 0.0f;
        const float sim_loss   = -S / (float)Bn;
        const float combined   = hinge_loss + bce_loss + sim_loss;
        out[0] = combined;
        out[1] = hinge_loss;
        out[2] = bce_loss;
        out[3] = sim_loss;
    }
}

extern "C" void kernel_launch(void* const* d_in, const int* in_sizes, int n_in,
                              void* d_out, int out_size)
{
    const float4* scores4 = (const float4*)d_in[0];
    const int*    lens    = (const int*)d_in[1];
    const float4* labels4 = (const float4*)d_in[2];
    const float*  sim     = (const float*)d_in[3];
    float* out = (float*)d_out;

    row_kernel<<<Bn, THREADS>>>(scores4, lens, labels4);
    final_kernel<<<1, 1024>>>(sim, out);
}